// round 15
// baseline (speedup 1.0000x reference)
#include <cuda_runtime.h>

#define S_ 8
#define U_ 32
#define V_ 32
#define C_ 32
#define SU 256              // S_*U_
#define SV 256              // S_*V_
#define WSEG (S_*U_*V_)     // 8192 floats per segment
#define WS_STRIDE 514       // u64 per s-slice: 512 + 2 pad
#define XW_F4 256           // per-warp x buffer: 4 rows * 64 float4 = 4 KB
#define NBLOCKS 592         // 4 per SM on 148 SMs
#define SMEM_BYTES (S_ * WS_STRIDE * 8 + 4 * XW_F4 * 16)   // 49,280 B

// Warp = 8 s x 4 vq; thread computes 4 rows x 8 v. Occupancy play vs R12:
// halved row-tile -> 32-reg acc file + 4KB x-buf -> 4 blocks/SM, 16 warps
// (was 10), reg cap 128 with ~80 live (first unpinned config).
// W premultiplied in padded SMEM (2 LDS.128/u, reused over 4 rows); x staged
// per-warp in swizzled SMEM so the compute loop has no long-latency loads.
__global__ __launch_bounds__(128, 4)
void idxlin_kernel(const float* __restrict__ W,     // (C, S*U*V)
                   const float* __restrict__ X,     // (Z, S*U)
                   const int*   __restrict__ counts,
                   const float* __restrict__ coef,
                   float* __restrict__ out,         // (Z, S*V)
                   int Z)
{
    extern __shared__ __align__(16) unsigned long long dynsm[];
    unsigned long long* w_sh = dynsm;                       // 8*514 u64
    __shared__ int segStart[C_ + 1];

    const int tid = threadIdx.x;
    if (tid == 0) {
        int a = 0; segStart[0] = 0;
        #pragma unroll
        for (int c = 0; c < C_; ++c) { a += counts[c]; segStart[c + 1] = a; }
    }
    __syncthreads();

    const int lane = tid & 31;
    const int wid  = tid >> 5;      // 4 warps
    const int s    = lane & 7;
    const int vq   = lane >> 3;     // 0..3 -> v-group of 8

    float4* xw = reinterpret_cast<float4*>(dynsm + S_ * WS_STRIDE) + wid * XW_F4;

    const int rpb = (Z + NBLOCKS - 1) / NBLOCKS;
    const int lo  = blockIdx.x * rpb;
    const int hi  = min(lo + rpb, Z);
    if (lo >= Z) return;

    int seg = 0;
    while (seg < C_ - 1 && segStart[seg + 1] <= lo) seg++;

    int cur = lo;
    while (cur < hi) {
        const int segTop = (seg < C_ - 1) ? segStart[seg + 1] : Z;
        const int e = min(segTop, hi);

        // ---- stage premultiplied W[seg] into padded SMEM (coalesced) ----
        __syncthreads();
        {
            const float4* wg = reinterpret_cast<const float4*>(W + (size_t)seg * WSEG);
            #pragma unroll
            for (int k = 0; k < WSEG / 4 / 128; ++k) {      // 16 iters
                const int idx4 = tid + 128 * k;
                float4 w = wg[idx4];
                const int ss  = idx4 >> 8;
                const int rem = idx4 & 255;
                const float c0 = coef[ss];
                w.x *= c0; w.y *= c0; w.z *= c0; w.w *= c0;
                *reinterpret_cast<float4*>(&w_sh[ss * WS_STRIDE + rem * 2]) = w;
            }
        }
        __syncthreads();

        // This thread's W view: s-slice + vq chunk; u-stride = 8 ulonglong2.
        const ulonglong2* wp = reinterpret_cast<const ulonglong2*>(
            &w_sh[s * WS_STRIDE + vq * 4]);

        // ---- row loop: each warp takes 4 consecutive rows ----
        for (int r0 = cur + wid * 4; r0 < e; r0 += 4 * 4) {
            const int rmax = min(3, e - 1 - r0);

            // ---- stage 4 rows of x into per-warp swizzled SMEM ----
            __syncwarp();   // prior compute done reading xw
            {
                const float4* Xg = reinterpret_cast<const float4*>(X)
                                   + (size_t)r0 * 64;
                #pragma unroll
                for (int k = 0; k < 8; ++k) {
                    const int g   = k * 32 + lane;      // linear float4 idx
                    const int row = g >> 6;
                    const int su4 = g & 63;
                    const int crow = row <= rmax ? row : rmax;
                    float4 v = Xg[(size_t)crow * 64 + su4];
                    // swizzle: low3 ^= s  ((g>>3)&7 == s within a row)
                    const int F = (g & ~7) | ((g & 7) ^ ((g >> 3) & 7));
                    xw[F] = v;
                }
            }
            __syncwarp();

            const float4* xr = xw + 8 * s;   // this thread's s-chunk base

            unsigned long long A00=0,A01=0,A02=0,A03=0, A10=0,A11=0,A12=0,A13=0,
                               A20=0,A21=0,A22=0,A23=0, A30=0,A31=0,A32=0,A33=0;

#define FMA2(acc, xx, ww) \
    asm("fma.rn.f32x2 %0, %1, %2, %0;" : "+l"(acc) : "l"(xx), "l"(ww));
// One row in a 4-u chunk: 1 broadcast LDS.128 of x, 16 FFMA2 vs held w.
#define DO_ROW(B0,B1,B2,B3, rr)                                                \
    {   float4 xq = xr[(rr) * 64 + xo];                                        \
        unsigned long long xx;                                                 \
        asm("mov.b64 %0, {%1, %1};" : "=l"(xx) : "f"(xq.x));                   \
        FMA2(B0, xx, wA.x) FMA2(B1, xx, wA.y) FMA2(B2, xx, wB.x) FMA2(B3, xx, wB.y) \
        asm("mov.b64 %0, {%1, %1};" : "=l"(xx) : "f"(xq.y));                   \
        FMA2(B0, xx, wC.x) FMA2(B1, xx, wC.y) FMA2(B2, xx, wD.x) FMA2(B3, xx, wD.y) \
        asm("mov.b64 %0, {%1, %1};" : "=l"(xx) : "f"(xq.z));                   \
        FMA2(B0, xx, wE.x) FMA2(B1, xx, wE.y) FMA2(B2, xx, wF.x) FMA2(B3, xx, wF.y) \
        asm("mov.b64 %0, {%1, %1};" : "=l"(xx) : "f"(xq.w));                   \
        FMA2(B0, xx, wG.x) FMA2(B1, xx, wG.y) FMA2(B2, xx, wH.x) FMA2(B3, xx, wH.y) \
    }

            #pragma unroll
            for (int uc = 0; uc < 8; ++uc) {
                const ulonglong2* wc = wp + uc * 32;     // u-stride 8 u2
                ulonglong2 wA = wc[0],  wB = wc[1];      // u = 4*uc
                ulonglong2 wC = wc[8],  wD = wc[9];      // u = 4*uc+1
                ulonglong2 wE = wc[16], wF = wc[17];     // u = 4*uc+2
                ulonglong2 wG = wc[24], wH = wc[25];     // u = 4*uc+3
                const int xo = uc ^ s;                   // swizzled chunk idx
                DO_ROW(A00,A01,A02,A03, 0)
                DO_ROW(A10,A11,A12,A13, 1)
                DO_ROW(A20,A21,A22,A23, 2)
                DO_ROW(A30,A31,A32,A33, 3)
                asm volatile("" ::: "memory");  // cap the scheduling window
            }
#undef DO_ROW
#undef FMA2

            // Stores: out[r][s*32 + vq*8 + 0..7], two float4 per row.
            float4* ob = reinterpret_cast<float4*>(
                out + (size_t)r0 * SV + s * V_ + vq * 8);
            float2 pa, pb;
#define STORE_ROW(rr, B0,B1,B2,B3)                                             \
    if (rr <= rmax) {                                                          \
        pa = *reinterpret_cast<float2*>(&B0);                                  \
        pb = *reinterpret_cast<float2*>(&B1);                                  \
        ob[rr * 64 + 0] = make_float4(pa.x, pa.y, pb.x, pb.y);                 \
        pa = *reinterpret_cast<float2*>(&B2);                                  \
        pb = *reinterpret_cast<float2*>(&B3);                                  \
        ob[rr * 64 + 1] = make_float4(pa.x, pa.y, pb.x, pb.y);                 \
    }
            STORE_ROW(0, A00,A01,A02,A03) STORE_ROW(1, A10,A11,A12,A13)
            STORE_ROW(2, A20,A21,A22,A23) STORE_ROW(3, A30,A31,A32,A33)
#undef STORE_ROW
        }

        cur = e;
        seg++;
        if (seg >= C_ && cur < hi) break;  // safety if counts undersum
    }
}

extern "C" void kernel_launch(void* const* d_in, const int* in_sizes, int n_in,
                              void* d_out, int out_size) {
    const float* W      = (const float*)d_in[0];   // input1 (C, S*U*V)
    const float* X      = (const float*)d_in[1];   // input2 (Z, S*U)
    const int*   counts = (const int*)d_in[2];
    const float* coef   = (const float*)d_in[3];
    float* out = (float*)d_out;

    cudaFuncSetAttribute(idxlin_kernel,
                         cudaFuncAttributeMaxDynamicSharedMemorySize,
                         SMEM_BYTES);

    int Z = in_sizes[1] / SU;
    idxlin_kernel<<<NBLOCKS, 128, SMEM_BYTES>>>(W, X, counts, coef, out, Z);
}

// round 17
// speedup vs baseline: 1.3834x; 1.3834x over previous
#include <cuda_runtime.h>
#include <cuda_bf16.h>
#include <cstdint>

#define S_ 8
#define U_ 32
#define V_ 32
#define C_ 32
#define SU 256
#define SV 256
#define WSEG 8192           // floats per segment
#define RPB 64              // rows per block
#define NT 4                // n-tiles of 8 (V=32)
#define MT 4                // m-tiles of 16 (64 rows)

// Split fp32 pair (x0,x1) into bf16x2 hi + exact-residual bf16x2 lo.
// cvt.rn.bf16x2.f32 d, a, b  ->  d.hi = bf16(a), d.lo = bf16(b)
__device__ __forceinline__ void split2(float x0, float x1,
                                       uint32_t& hi, uint32_t& lo) {
    asm("cvt.rn.bf16x2.f32 %0, %1, %2;" : "=r"(hi) : "f"(x1), "f"(x0));
    float f0 = __uint_as_float(hi << 16);          // float value of bf16(x0)
    float f1 = __uint_as_float(hi & 0xFFFF0000u);  // float value of bf16(x1)
    float r0 = x0 - f0;                            // exact in fp32
    float r1 = x1 - f1;
    asm("cvt.rn.bf16x2.f32 %0, %1, %2;" : "=r"(lo) : "f"(r1), "f"(r0));
}

#define MMA(d, a0,a1,a2,a3, b0,b1)                                         \
    asm volatile("mma.sync.aligned.m16n8k16.row.col.f32.bf16.bf16.f32 "    \
        "{%0,%1,%2,%3}, {%4,%5,%6,%7}, {%8,%9}, {%0,%1,%2,%3};"            \
        : "+f"(d[0]), "+f"(d[1]), "+f"(d[2]), "+f"(d[3])                   \
        : "r"(a0), "r"(a1), "r"(a2), "r"(a3), "r"(b0), "r"(b1));

// Warp = one s. CTA = 8 warps x 64 rows. No SMEM staging: A fragments are
// k-contiguous pairs -> LDG.64 from X; C pairs are v-contiguous -> STG.64.
// bf16x3 products (AhBh + AhBl + AlBh) accumulate in fp32.
__global__ __launch_bounds__(256, 2)
void idxlin_hmma(const float* __restrict__ W, const float* __restrict__ X,
                 const int* __restrict__ counts, const float* __restrict__ coef,
                 float* __restrict__ out, int Z)
{
    __shared__ int segStart[C_ + 1];
    const int tid = threadIdx.x, lane = tid & 31, s = tid >> 5;
    if (tid == 0) {
        int a = 0; segStart[0] = 0;
        #pragma unroll
        for (int c = 0; c < C_; ++c) { a += counts[c]; segStart[c + 1] = a; }
    }
    __syncthreads();

    const int r0 = blockIdx.x * RPB;
    if (r0 >= Z) return;
    const int tileEnd = min(r0 + RPB, Z);
    const int qrow = lane >> 2;        // 0..7
    const int kp   = (lane & 3) * 2;   // k-pair base
    const float cf = coef[s];

    int pl = r0, seg = 0;
    while (seg < C_ - 1 && segStart[seg + 1] <= pl) seg++;

    while (pl < tileEnd) {
        const int segTop = (seg < C_ - 1) ? segStart[seg + 1] : Z;
        const int pr = min(segTop, tileEnd);

        // ---- B fragments for W[seg], premultiplied by coef[s] ----
        // b(h): k = kt*16 + h*8 + kp + {0,1},  n = nt*8 + qrow
        uint32_t BH[NT][2][2], BL[NT][2][2];
        {
            const float* Wp = W + (size_t)seg * WSEG + s * (U_ * V_);
            #pragma unroll
            for (int n = 0; n < NT; ++n) {
                const int v = n * 8 + qrow;
                #pragma unroll
                for (int kt = 0; kt < 2; ++kt) {
                    #pragma unroll
                    for (int h = 0; h < 2; ++h) {
                        const int u0 = kt * 16 + h * 8 + kp;
                        float w0 = Wp[u0 * V_ + v] * cf;
                        float w1 = Wp[(u0 + 1) * V_ + v] * cf;
                        split2(w0, w1, BH[n][kt][h], BL[n][kt][h]);
                    }
                }
            }
        }

        // ---- M-tiles: load A from gmem, 24 HMMA, masked stores ----
        #pragma unroll
        for (int m = 0; m < MT; ++m) {
            const int row  = r0 + m * 16 + qrow;
            const int rowc  = min(row,     Z - 1);
            const int rowc8 = min(row + 8, Z - 1);
            const float* Xr  = X + (size_t)rowc  * SU + s * U_;
            const float* Xr8 = X + (size_t)rowc8 * SU + s * U_;

            // A frags: a0=(row,k0-7) a1=(row+8,k0-7) a2=(row,k8-15) a3=(row+8,k8-15)
            uint32_t AH[2][4], AL[2][4];
            #pragma unroll
            for (int kt = 0; kt < 2; ++kt) {
                float2 e0 = *reinterpret_cast<const float2*>(Xr  + kt * 16 + kp);
                float2 e1 = *reinterpret_cast<const float2*>(Xr8 + kt * 16 + kp);
                float2 e2 = *reinterpret_cast<const float2*>(Xr  + kt * 16 + 8 + kp);
                float2 e3 = *reinterpret_cast<const float2*>(Xr8 + kt * 16 + 8 + kp);
                split2(e0.x, e0.y, AH[kt][0], AL[kt][0]);
                split2(e1.x, e1.y, AH[kt][1], AL[kt][1]);
                split2(e2.x, e2.y, AH[kt][2], AL[kt][2]);
                split2(e3.x, e3.y, AH[kt][3], AL[kt][3]);
            }

            float acc[NT][4];
            #pragma unroll
            for (int n = 0; n < NT; ++n)
                { acc[n][0]=0.f; acc[n][1]=0.f; acc[n][2]=0.f; acc[n][3]=0.f; }

            #pragma unroll
            for (int n = 0; n < NT; ++n) {
                #pragma unroll
                for (int kt = 0; kt < 2; ++kt) {
                    MMA(acc[n], AH[kt][0],AH[kt][1],AH[kt][2],AH[kt][3],
                        BH[n][kt][0], BH[n][kt][1]);
                    MMA(acc[n], AH[kt][0],AH[kt][1],AH[kt][2],AH[kt][3],
                        BL[n][kt][0], BL[n][kt][1]);
                    MMA(acc[n], AL[kt][0],AL[kt][1],AL[kt][2],AL[kt][3],
                        BH[n][kt][0], BH[n][kt][1]);
                }
            }

            // C frags: {c0,c1} row, cols kp,kp+1 ; {c2,c3} row+8.
            const bool st0 = (row     >= pl) && (row     < pr);
            const bool st1 = (row + 8 >= pl) && (row + 8 < pr);
            float* ob  = out + (size_t)row * SV + s * V_ + kp;
            float* ob8 = out + (size_t)(row + 8) * SV + s * V_ + kp;
            #pragma unroll
            for (int n = 0; n < NT; ++n) {
                if (st0)
                    *reinterpret_cast<float2*>(ob + n * 8)
                        = make_float2(acc[n][0], acc[n][1]);
                if (st1)
                    *reinterpret_cast<float2*>(ob8 + n * 8)
                        = make_float2(acc[n][2], acc[n][3]);
            }
        }

        pl = pr;
        seg++;
        if (seg > C_) break;   // safety if counts undersum
    }
}

extern "C" void kernel_launch(void* const* d_in, const int* in_sizes, int n_in,
                              void* d_out, int out_size) {
    const float* W      = (const float*)d_in[0];   // input1 (C, S*U*V)
    const float* X      = (const float*)d_in[1];   // input2 (Z, S*U)
    const int*   counts = (const int*)d_in[2];
    const float* coef   = (const float*)d_in[3];
    float* out = (float*)d_out;

    int Z = in_sizes[1] / SU;
    int grid = (Z + RPB - 1) / RPB;
    idxlin_hmma<<<grid, 256>>>(W, X, counts, coef, out, Z);
}